// round 9
// baseline (speedup 1.0000x reference)
#include <cuda_runtime.h>

// YOLO loss reduction: prediction/target (16384, 6, 6, 106) fp32 -> 6 fp32 scalars.
// Pass 1: one warp per cell-pair, 8 front-batched LDG.64 per iteration (MLP=8).
//   Row = 106 floats = 53 float2, 8B-aligned for every cell. Pass 0: lanes 0-31
//   -> float2[0..31] (ch 0-63); pass 1: lanes 0-20 -> float2[32..52] (ch 64-105).
//   Lane roles: lane0={x,y}, lane1={w,h}, lane2={conf,class}, rest class.
//   Deterministic block combine (shuffle -> per-warp shared -> fixed-order sum),
//   5 partials per block to __device__ scratch. No atomics anywhere.
// Pass 2: single block deterministically reduces 4736x5 partials + finalizes.
// Grid = 148 SMs * 32 = 4736 blocks: full waves at occ 4/8, <=4% tail at occ 6.

#define CH 106
#define F2_PER_CELL 53
#define GRID_BLOCKS 4736
#define WARPS_PER_BLOCK 8

__device__ float g_part[5][GRID_BLOCKS];   // per-block partials (SoA)

struct CellErr {
    float xy, wh, conf, cls, tc;
};

__device__ __forceinline__ CellErr cell_compute(
    int lane, float2 t0, float2 p0, float2 t1, float2 p1)
{
    CellErr e{0.f, 0.f, 0.f, 0.f, 0.f};

    const float d0 = t0.x - p0.x;
    const float d1 = t0.y - p0.y;
    if (lane == 0) {                       // channels 0,1: x,y
        e.xy = d0 * d0 + d1 * d1;
    } else if (lane == 1) {                // channels 2,3: w,h
        float s0 = sqrtf(t0.x) - sqrtf(fmaxf(p0.x, 0.f));
        float s1 = sqrtf(t0.y) - sqrtf(fmaxf(p0.y, 0.f));
        e.wh = s0 * s0 + s1 * s1;
    } else if (lane == 2) {                // ch 4: conf, ch 5: class
        e.tc = t0.x;
        e.conf = d0 * d0;
        e.cls = d1 * d1;
    } else {                               // ch 6..63: class
        e.cls = d0 * d0 + d1 * d1;
    }
    // channels 64..105: class (zero for lanes >= 21 via zero-filled t1/p1)
    const float d2 = t1.x - p1.x;
    const float d3 = t1.y - p1.y;
    e.cls += d2 * d2 + d3 * d3;
    return e;
}

__global__ void __launch_bounds__(256) yolo_loss_kernel(
    const float* __restrict__ pred,
    const float* __restrict__ targ,
    int n_cells)
{
    const int lane = threadIdx.x & 31;
    const int wib  = threadIdx.x >> 5;             // warp index in block
    const int warp_id = blockIdx.x * WARPS_PER_BLOCK + wib;
    const int n_warps = gridDim.x * WARPS_PER_BLOCK;

    float a_xy = 0.f, a_wh = 0.f, a_co = 0.f, a_cn = 0.f, a_cls = 0.f;

    const bool has2 = (lane < F2_PER_CELL - 32);   // lanes 0..20 do pass 1
    const float2 z2 = make_float2(0.f, 0.f);

    const int n_pairs = n_cells >> 1;

    for (int pair = warp_id; pair < n_pairs; pair += n_warps) {
        const size_t base = (size_t)pair * (2 * CH);
        const float2* __restrict__ tpa = (const float2*)(targ + base);
        const float2* __restrict__ ppa = (const float2*)(pred + base);
        const float2* __restrict__ tpb = (const float2*)(targ + base + CH);
        const float2* __restrict__ ppb = (const float2*)(pred + base + CH);

        // front-batch all 8 loads (both cells) before any math
        float2 ta0 = tpa[lane];
        float2 pa0 = ppa[lane];
        float2 tb0 = tpb[lane];
        float2 pb0 = ppb[lane];
        float2 ta1 = has2 ? tpa[32 + lane] : z2;
        float2 pa1 = has2 ? ppa[32 + lane] : z2;
        float2 tb1 = has2 ? tpb[32 + lane] : z2;
        float2 pb1 = has2 ? ppb[32 + lane] : z2;

        CellErr ea = cell_compute(lane, ta0, pa0, ta1, pa1);
        CellErr eb = cell_compute(lane, tb0, pb0, tb1, pb1);

        const float tca = __shfl_sync(0xffffffffu, ea.tc, 2);
        const float tcb = __shfl_sync(0xffffffffu, eb.tc, 2);
        const float obja = (tca != 0.f) ? 1.f : 0.f;
        const float objb = (tcb != 0.f) ? 1.f : 0.f;

        a_xy  += obja * ea.xy   + objb * eb.xy;
        a_wh  += obja * ea.wh   + objb * eb.wh;
        a_cls += obja * ea.cls  + objb * eb.cls;
        a_co  += obja * ea.conf + objb * eb.conf;
        a_cn  += (1.f - obja) * ea.conf + (1.f - objb) * eb.conf;
    }

    // odd tail cell (n_cells odd): handled once by warp 0
    if ((n_cells & 1) && warp_id == 0) {
        const int cell = n_cells - 1;
        const float2* __restrict__ tp = (const float2*)(targ + (size_t)cell * CH);
        const float2* __restrict__ pp = (const float2*)(pred + (size_t)cell * CH);
        float2 t0 = tp[lane];
        float2 p0 = pp[lane];
        float2 t1 = has2 ? tp[32 + lane] : z2;
        float2 p1 = has2 ? pp[32 + lane] : z2;
        CellErr e = cell_compute(lane, t0, p0, t1, p1);
        const float tc = __shfl_sync(0xffffffffu, e.tc, 2);
        const float obj = (tc != 0.f) ? 1.f : 0.f;
        a_xy  += obj * e.xy;
        a_wh  += obj * e.wh;
        a_cls += obj * e.cls;
        a_co  += obj * e.conf;
        a_cn  += (1.f - obj) * e.conf;
    }

    // warp tree-reduce (deterministic shuffle order)
    #pragma unroll
    for (int off = 16; off > 0; off >>= 1) {
        a_xy  += __shfl_xor_sync(0xffffffffu, a_xy,  off);
        a_wh  += __shfl_xor_sync(0xffffffffu, a_wh,  off);
        a_co  += __shfl_xor_sync(0xffffffffu, a_co,  off);
        a_cn  += __shfl_xor_sync(0xffffffffu, a_cn,  off);
        a_cls += __shfl_xor_sync(0xffffffffu, a_cls, off);
    }

    // deterministic block combine: per-warp slots, fixed-order sum
    __shared__ float s_warp[WARPS_PER_BLOCK][5];
    if (lane == 0) {
        s_warp[wib][0] = a_xy;
        s_warp[wib][1] = a_wh;
        s_warp[wib][2] = a_co;
        s_warp[wib][3] = a_cn;
        s_warp[wib][4] = a_cls;
    }
    __syncthreads();

    if (threadIdx.x < 5) {
        float s = 0.f;
        #pragma unroll
        for (int w = 0; w < WARPS_PER_BLOCK; w++) s += s_warp[w][threadIdx.x];
        g_part[threadIdx.x][blockIdx.x] = s;
    }
}

__global__ void __launch_bounds__(256) yolo_reduce_kernel(
    float* __restrict__ out, float invB)
{
    const int tid = threadIdx.x;
    const int lane = tid & 31;
    const int wib = tid >> 5;

    // per-thread strided accumulation (fixed order per thread)
    float acc[5] = {0.f, 0.f, 0.f, 0.f, 0.f};
    for (int i = tid; i < GRID_BLOCKS; i += 256) {
        #pragma unroll
        for (int c = 0; c < 5; c++) acc[c] += g_part[c][i];
    }

    // deterministic warp shuffle reduce
    #pragma unroll
    for (int off = 16; off > 0; off >>= 1) {
        #pragma unroll
        for (int c = 0; c < 5; c++)
            acc[c] += __shfl_xor_sync(0xffffffffu, acc[c], off);
    }

    __shared__ float s_warp[8][5];
    if (lane == 0) {
        #pragma unroll
        for (int c = 0; c < 5; c++) s_warp[wib][c] = acc[c];
    }
    __syncthreads();

    if (tid == 0) {
        float tot[5];
        #pragma unroll
        for (int c = 0; c < 5; c++) {
            float s = 0.f;
            #pragma unroll
            for (int w = 0; w < 8; w++) s += s_warp[w][c];
            tot[c] = s * invB;
        }
        out[0] = tot[0];
        out[1] = tot[1];
        out[2] = tot[2];
        out[3] = tot[3];
        out[4] = tot[4];
        out[5] = (5.0f * tot[0] + 5.0f * tot[1] + tot[2]
                  + 0.5f * tot[3] + tot[4]) * invB;
    }
}

extern "C" void kernel_launch(void* const* d_in, const int* in_sizes, int n_in,
                              void* d_out, int out_size)
{
    const float* pred = (const float*)d_in[0];
    const float* targ = (const float*)d_in[1];
    float* out = (float*)d_out;

    const int n_cells = in_sizes[0] / CH;          // 16384 * 36 = 589824
    const int B = n_cells / 36;                    // batch = 16384 (S=6)
    const float invB = 1.0f / (float)B;

    yolo_loss_kernel<<<GRID_BLOCKS, 256>>>(pred, targ, n_cells);
    yolo_reduce_kernel<<<1, 256>>>(out, invB);
}

// round 10
// speedup vs baseline: 1.0421x; 1.0421x over previous
#include <cuda_runtime.h>

// YOLO loss reduction: prediction/target (16384, 6, 6, 106) fp32 -> 6 fp32 scalars.
// Single fused kernel (last-block-finishes):
//   Main loop: one warp per cell-pair, 8 front-batched LDG.64 per iteration
//   (MLP=8). Row = 106 floats = 53 float2, 8B-aligned. Pass 0: lanes 0-31 ->
//   float2[0..31] (ch 0-63); pass 1: lanes 0-20 -> float2[32..52] (ch 64-105).
//   Lane roles: lane0={x,y}, lane1={w,h}, lane2={conf,class}, rest class.
//   Deterministic block combine -> 5 partials per block -> __device__ scratch.
//   Last block (atomic counter) reduces all partials in FIXED order (bitwise
//   deterministic), finalizes, writes 6 outputs, resets counter (replay-safe).
// Grid = 148 SMs * 32 = 4736 blocks. R9 measured: 2-kernel version 91.9us with
// 14.4us spent in the separate reduce launch -> fusion removes that.

#define CH 106
#define F2_PER_CELL 53
#define GRID_BLOCKS 4736
#define WARPS_PER_BLOCK 8
#define BLOCK_THREADS 256
#define FULL_ROUNDS (GRID_BLOCKS / BLOCK_THREADS)            // 18
#define TAIL_COUNT (GRID_BLOCKS - FULL_ROUNDS * BLOCK_THREADS) // 128

__device__ float g_part[5][GRID_BLOCKS];   // per-block partials (SoA)
__device__ unsigned int g_count = 0;       // self-resetting arrival counter

struct CellErr {
    float xy, wh, conf, cls, tc;
};

__device__ __forceinline__ CellErr cell_compute(
    int lane, float2 t0, float2 p0, float2 t1, float2 p1)
{
    CellErr e{0.f, 0.f, 0.f, 0.f, 0.f};

    const float d0 = t0.x - p0.x;
    const float d1 = t0.y - p0.y;
    if (lane == 0) {                       // channels 0,1: x,y
        e.xy = d0 * d0 + d1 * d1;
    } else if (lane == 1) {                // channels 2,3: w,h
        float s0 = sqrtf(t0.x) - sqrtf(fmaxf(p0.x, 0.f));
        float s1 = sqrtf(t0.y) - sqrtf(fmaxf(p0.y, 0.f));
        e.wh = s0 * s0 + s1 * s1;
    } else if (lane == 2) {                // ch 4: conf, ch 5: class
        e.tc = t0.x;
        e.conf = d0 * d0;
        e.cls = d1 * d1;
    } else {                               // ch 6..63: class
        e.cls = d0 * d0 + d1 * d1;
    }
    // channels 64..105: class (zero for lanes >= 21 via zero-filled t1/p1)
    const float d2 = t1.x - p1.x;
    const float d3 = t1.y - p1.y;
    e.cls += d2 * d2 + d3 * d3;
    return e;
}

__global__ void __launch_bounds__(BLOCK_THREADS) yolo_loss_kernel(
    const float* __restrict__ pred,
    const float* __restrict__ targ,
    int n_cells,
    float invB,
    float* __restrict__ out)
{
    const int lane = threadIdx.x & 31;
    const int wib  = threadIdx.x >> 5;             // warp index in block
    const int warp_id = blockIdx.x * WARPS_PER_BLOCK + wib;
    const int n_warps = gridDim.x * WARPS_PER_BLOCK;

    float a_xy = 0.f, a_wh = 0.f, a_co = 0.f, a_cn = 0.f, a_cls = 0.f;

    const bool has2 = (lane < F2_PER_CELL - 32);   // lanes 0..20 do pass 1
    const float2 z2 = make_float2(0.f, 0.f);

    const int n_pairs = n_cells >> 1;

    for (int pair = warp_id; pair < n_pairs; pair += n_warps) {
        const size_t base = (size_t)pair * (2 * CH);
        const float2* __restrict__ tpa = (const float2*)(targ + base);
        const float2* __restrict__ ppa = (const float2*)(pred + base);
        const float2* __restrict__ tpb = (const float2*)(targ + base + CH);
        const float2* __restrict__ ppb = (const float2*)(pred + base + CH);

        // front-batch all 8 loads (both cells) before any math
        float2 ta0 = tpa[lane];
        float2 pa0 = ppa[lane];
        float2 tb0 = tpb[lane];
        float2 pb0 = ppb[lane];
        float2 ta1 = has2 ? tpa[32 + lane] : z2;
        float2 pa1 = has2 ? ppa[32 + lane] : z2;
        float2 tb1 = has2 ? tpb[32 + lane] : z2;
        float2 pb1 = has2 ? ppb[32 + lane] : z2;

        CellErr ea = cell_compute(lane, ta0, pa0, ta1, pa1);
        CellErr eb = cell_compute(lane, tb0, pb0, tb1, pb1);

        const float tca = __shfl_sync(0xffffffffu, ea.tc, 2);
        const float tcb = __shfl_sync(0xffffffffu, eb.tc, 2);
        const float obja = (tca != 0.f) ? 1.f : 0.f;
        const float objb = (tcb != 0.f) ? 1.f : 0.f;

        a_xy  += obja * ea.xy   + objb * eb.xy;
        a_wh  += obja * ea.wh   + objb * eb.wh;
        a_cls += obja * ea.cls  + objb * eb.cls;
        a_co  += obja * ea.conf + objb * eb.conf;
        a_cn  += (1.f - obja) * ea.conf + (1.f - objb) * eb.conf;
    }

    // odd tail cell (n_cells odd): handled once by warp 0
    if ((n_cells & 1) && warp_id == 0) {
        const int cell = n_cells - 1;
        const float2* __restrict__ tp = (const float2*)(targ + (size_t)cell * CH);
        const float2* __restrict__ pp = (const float2*)(pred + (size_t)cell * CH);
        float2 t0 = tp[lane];
        float2 p0 = pp[lane];
        float2 t1 = has2 ? tp[32 + lane] : z2;
        float2 p1 = has2 ? pp[32 + lane] : z2;
        CellErr e = cell_compute(lane, t0, p0, t1, p1);
        const float tc = __shfl_sync(0xffffffffu, e.tc, 2);
        const float obj = (tc != 0.f) ? 1.f : 0.f;
        a_xy  += obj * e.xy;
        a_wh  += obj * e.wh;
        a_cls += obj * e.cls;
        a_co  += obj * e.conf;
        a_cn  += (1.f - obj) * e.conf;
    }

    // warp tree-reduce (deterministic shuffle order)
    #pragma unroll
    for (int off = 16; off > 0; off >>= 1) {
        a_xy  += __shfl_xor_sync(0xffffffffu, a_xy,  off);
        a_wh  += __shfl_xor_sync(0xffffffffu, a_wh,  off);
        a_co  += __shfl_xor_sync(0xffffffffu, a_co,  off);
        a_cn  += __shfl_xor_sync(0xffffffffu, a_cn,  off);
        a_cls += __shfl_xor_sync(0xffffffffu, a_cls, off);
    }

    // deterministic block combine: per-warp slots, fixed-order sum
    __shared__ float s_warp[WARPS_PER_BLOCK][5];
    if (lane == 0) {
        s_warp[wib][0] = a_xy;
        s_warp[wib][1] = a_wh;
        s_warp[wib][2] = a_co;
        s_warp[wib][3] = a_cn;
        s_warp[wib][4] = a_cls;
    }
    __syncthreads();

    if (threadIdx.x < 5) {
        float s = 0.f;
        #pragma unroll
        for (int w = 0; w < WARPS_PER_BLOCK; w++) s += s_warp[w][threadIdx.x];
        g_part[threadIdx.x][blockIdx.x] = s;
    }

    // ---- last-block-finishes final reduction ----
    __shared__ bool s_is_last;
    __threadfence();                                 // publish partials
    if (threadIdx.x == 0) {
        unsigned int prev = atomicAdd(&g_count, 1u);
        s_is_last = (prev == (unsigned int)(gridDim.x - 1));
    }
    __syncthreads();
    if (!s_is_last) return;

    __threadfence();                                 // acquire all partials

    const int tid = threadIdx.x;

    // fixed-order accumulation: thread t sums entries t, t+256, ... (order
    // independent of which block executes this -> bitwise deterministic)
    float acc[5] = {0.f, 0.f, 0.f, 0.f, 0.f};
    #pragma unroll
    for (int k = 0; k < FULL_ROUNDS; k++) {
        const int i = tid + k * BLOCK_THREADS;
        #pragma unroll
        for (int c = 0; c < 5; c++) acc[c] += g_part[c][i];
    }
    if (tid < TAIL_COUNT) {
        const int i = tid + FULL_ROUNDS * BLOCK_THREADS;
        #pragma unroll
        for (int c = 0; c < 5; c++) acc[c] += g_part[c][i];
    }

    // deterministic warp shuffle reduce
    #pragma unroll
    for (int off = 16; off > 0; off >>= 1) {
        #pragma unroll
        for (int c = 0; c < 5; c++)
            acc[c] += __shfl_xor_sync(0xffffffffu, acc[c], off);
    }

    __shared__ float s_fin[WARPS_PER_BLOCK][5];
    if (lane == 0) {
        #pragma unroll
        for (int c = 0; c < 5; c++) s_fin[wib][c] = acc[c];
    }
    __syncthreads();

    if (tid == 0) {
        float tot[5];
        #pragma unroll
        for (int c = 0; c < 5; c++) {
            float s = 0.f;
            #pragma unroll
            for (int w = 0; w < WARPS_PER_BLOCK; w++) s += s_fin[w][c];
            tot[c] = s * invB;
        }
        out[0] = tot[0];
        out[1] = tot[1];
        out[2] = tot[2];
        out[3] = tot[3];
        out[4] = tot[4];
        out[5] = (5.0f * tot[0] + 5.0f * tot[1] + tot[2]
                  + 0.5f * tot[3] + tot[4]) * invB;

        g_count = 0;                                 // reset for next replay
    }
}

extern "C" void kernel_launch(void* const* d_in, const int* in_sizes, int n_in,
                              void* d_out, int out_size)
{
    const float* pred = (const float*)d_in[0];
    const float* targ = (const float*)d_in[1];
    float* out = (float*)d_out;

    const int n_cells = in_sizes[0] / CH;          // 16384 * 36 = 589824
    const int B = n_cells / 36;                    // batch = 16384 (S=6)
    const float invB = 1.0f / (float)B;

    yolo_loss_kernel<<<GRID_BLOCKS, BLOCK_THREADS>>>(pred, targ, n_cells, invB, out);
}